// round 2
// baseline (speedup 1.0000x reference)
#include <cuda_runtime.h>

#define HW   4096
#define CCH  64
#define BB   4
#define KK   8

// Scratch (allocation-free rule: __device__ globals)
__device__ float g_f[BB * HW * KK];      // [b][n][k]  (n-major, 8 contiguous)
__device__ float g_g[BB * HW * KK];      // [b][n][k]
__device__ float g_h[BB * CCH * HW];     // [b][c][n]
__device__ float g_part[BB * 4 * HW];    // partial denom sums, 4 m-quarters
__device__ float g_rden[BB * HW];        // 1/denom per (b,n)

// ---------------------------------------------------------------------------
// Kernel A: f = Wf@x+bf, g = Wg@x+bg, h = Wh@x+bh   (1x1 convs over channels)
// grid (32 n-chunks, 4 b), 256 threads. Thread handles one n (of 128) and
// half the outputs: half0 -> h rows 0..31 + f[0..7]; half1 -> h 32..63 + g.
// ---------------------------------------------------------------------------
__global__ __launch_bounds__(256) void kA(
    const float* __restrict__ x,
    const float* __restrict__ Wf, const float* __restrict__ bf,
    const float* __restrict__ Wg, const float* __restrict__ bg,
    const float* __restrict__ Wh, const float* __restrict__ bh)
{
    __shared__ float xs[64 * 128];
    const int t  = threadIdx.x;
    const int b  = blockIdx.y;
    const int n0 = blockIdx.x * 128;

    // Load x tile [64 c][128 n], coalesced
    #pragma unroll
    for (int r = 0; r < 32; r++) {
        int lin = r * 256 + t;
        int c = lin >> 7, nn = lin & 127;
        xs[lin] = x[((b * 64 + c) << 12) + n0 + nn];
    }
    __syncthreads();

    const int n = t & 127, half = t >> 7;
    const int rowbase = half * 32;
    const float* Wfg = half ? Wg : Wf;
    const float* bfg = half ? bg : bf;

    float acch[32], accfg[8];
    #pragma unroll
    for (int o = 0; o < 32; o++) acch[o] = bh[rowbase + o];
    #pragma unroll
    for (int k = 0; k < 8; k++)  accfg[k] = bfg[k];

    #pragma unroll
    for (int c0 = 0; c0 < 64; c0 += 8) {
        float xv[8];
        #pragma unroll
        for (int j = 0; j < 8; j++) xv[j] = xs[(c0 + j) * 128 + n];

        #pragma unroll
        for (int o = 0; o < 32; o++) {
            const float4* w = (const float4*)(Wh + (rowbase + o) * 64 + c0);
            float4 w0 = w[0], w1 = w[1];
            acch[o] += w0.x * xv[0] + w0.y * xv[1] + w0.z * xv[2] + w0.w * xv[3]
                     + w1.x * xv[4] + w1.y * xv[5] + w1.z * xv[6] + w1.w * xv[7];
        }
        #pragma unroll
        for (int k = 0; k < 8; k++) {
            const float4* w = (const float4*)(Wfg + k * 64 + c0);
            float4 w0 = w[0], w1 = w[1];
            accfg[k] += w0.x * xv[0] + w0.y * xv[1] + w0.z * xv[2] + w0.w * xv[3]
                      + w1.x * xv[4] + w1.y * xv[5] + w1.z * xv[6] + w1.w * xv[7];
        }
    }

    const int ng = n0 + n;
    #pragma unroll
    for (int o = 0; o < 32; o++)
        g_h[((b * 64 + rowbase + o) << 12) + ng] = acch[o];

    float* dst = (half ? g_g : g_f) + (b * HW + ng) * 8;
    *(float4*)(dst)     = make_float4(accfg[0], accfg[1], accfg[2], accfg[3]);
    *(float4*)(dst + 4) = make_float4(accfg[4], accfg[5], accfg[6], accfg[7]);
}

// ---------------------------------------------------------------------------
// Kernel B1: partial denominators. denom[b][n] = sum_m exp(f_m . g_n)
// grid (16 n-chunks of 256, 4 m-quarters of 1024, 4 b), 256 threads.
// ---------------------------------------------------------------------------
__global__ __launch_bounds__(256) void kB1()
{
    __shared__ float fs[128 * 8];
    const int t  = threadIdx.x;
    const int b  = blockIdx.z;
    const int mq = blockIdx.y;
    const int n  = blockIdx.x * 256 + t;

    const float4* gp = (const float4*)&g_g[(b * HW + n) * 8];
    const float4 gv0 = gp[0], gv1 = gp[1];

    float acc0 = 0.f, acc1 = 0.f;
    const int mend = mq * 1024 + 1024;
    for (int m0 = mq * 1024; m0 < mend; m0 += 128) {
        ((float4*)fs)[t] = ((const float4*)&g_f[(b * HW + m0) * 8])[t];
        __syncthreads();
        #pragma unroll 8
        for (int mm = 0; mm < 128; mm += 2) {
            float4 f0 = *(float4*)&fs[mm * 8];
            float4 f1 = *(float4*)&fs[mm * 8 + 4];
            float s0 = f0.x * gv0.x + f0.y * gv0.y + f0.z * gv0.z + f0.w * gv0.w
                     + f1.x * gv1.x + f1.y * gv1.y + f1.z * gv1.z + f1.w * gv1.w;
            acc0 += __expf(s0);
            float4 h0 = *(float4*)&fs[(mm + 1) * 8];
            float4 h1 = *(float4*)&fs[(mm + 1) * 8 + 4];
            float s1 = h0.x * gv0.x + h0.y * gv0.y + h0.z * gv0.z + h0.w * gv0.w
                     + h1.x * gv1.x + h1.y * gv1.y + h1.z * gv1.z + h1.w * gv1.w;
            acc1 += __expf(s1);
        }
        __syncthreads();
    }
    g_part[(b * 4 + mq) * HW + n] = acc0 + acc1;
}

// Kernel B2: reduce quarters, reciprocal.
__global__ __launch_bounds__(256) void kB2()
{
    int i = blockIdx.x * 256 + threadIdx.x;      // 0..16383 = b*4096+n
    int b = i >> 12, n = i & 4095;
    float s = g_part[(b * 4 + 0) * HW + n] + g_part[(b * 4 + 1) * HW + n]
            + g_part[(b * 4 + 2) * HW + n] + g_part[(b * 4 + 3) * HW + n];
    g_rden[i] = 1.0f / s;
}

// ---------------------------------------------------------------------------
// Kernel C: O[c,m] = sum_{n>=m} exp(f_m.g_n) * h[c,n]/denom[n]; y = g*O + x.
// One block per (b, 64-row m-tile); loops n-tiles of 64 from the diagonal.
// Phase 1: P tile in smem (exp). Phase 2: 4x4 register-blocked fp32 GEMM.
// Task permutation pairs long tiles with short ones across occupancy slots.
// ---------------------------------------------------------------------------
__global__ __launch_bounds__(256) void kC(
    const float* __restrict__ x,
    const float* __restrict__ gamma,
    float* __restrict__ out)
{
    __shared__ float fs[64 * 8];
    __shared__ float gs[64 * 8];
    __shared__ float Pt[64 * 68];   // [n][m], padded
    __shared__ float Vt[64 * 68];   // [n][c], padded

    const int tid = threadIdx.x;
    const int bid = blockIdx.x;
    const int tsk = (bid < 128) ? bid : (383 - bid);   // descending-cost order
    const int mt = tsk >> 2, b = tsk & 3;
    const int m_base = mt * 64;

    // f tile [64 m][8], loaded once
    ((float2*)fs)[tid] = ((const float2*)&g_f[(b * HW + m_base) * 8])[tid];

    float acc[4][4];
    #pragma unroll
    for (int i = 0; i < 4; i++)
        #pragma unroll
        for (int j = 0; j < 4; j++) acc[i][j] = 0.f;

    const int tx = tid & 15, ty = tid >> 4;
    const int tc = tx * 4, tm = ty * 4;
    const int nloc = tid >> 2, mgrp = tid & 3;

    for (int n0 = m_base; n0 < HW; n0 += 64) {
        // g tile [64 n][8]
        ((float2*)gs)[tid] = ((const float2*)&g_g[(b * HW + n0) * 8])[tid];
        // V' tile: Vt[n][c] = h[b][c][n0+n] * rden[n0+n]  (coalesced over n)
        #pragma unroll
        for (int r = 0; r < 16; r++) {
            int lin = r * 256 + tid;
            int c = lin >> 6, nn = lin & 63;
            Vt[nn * 68 + c] = g_h[((b * 64 + c) << 12) + n0 + nn]
                            * g_rden[b * HW + n0 + nn];
        }
        __syncthreads();

        // Phase 1: P[n][m] = exp(f_m . g_n), masked to n >= m (only diag tile)
        {
            float4 gv0 = *(float4*)&gs[nloc * 8];
            float4 gv1 = *(float4*)&gs[nloc * 8 + 4];
            int ng = n0 + nloc;
            #pragma unroll
            for (int i = 0; i < 16; i++) {
                int mloc = mgrp * 16 + i;
                float4 f0 = *(float4*)&fs[mloc * 8];
                float4 f1 = *(float4*)&fs[mloc * 8 + 4];
                float s = f0.x * gv0.x + f0.y * gv0.y + f0.z * gv0.z + f0.w * gv0.w
                        + f1.x * gv1.x + f1.y * gv1.y + f1.z * gv1.z + f1.w * gv1.w;
                float p = __expf(s);
                if (ng < m_base + mloc) p = 0.f;
                Pt[nloc * 68 + mloc] = p;
            }
        }
        __syncthreads();

        // Phase 2: acc[m][c] += sum_n P[n][m] * V'[n][c]
        #pragma unroll 8
        for (int nn = 0; nn < 64; nn++) {
            float4 pv = *(float4*)&Pt[nn * 68 + tm];
            float4 vv = *(float4*)&Vt[nn * 68 + tc];
            acc[0][0] += pv.x * vv.x; acc[0][1] += pv.x * vv.y;
            acc[0][2] += pv.x * vv.z; acc[0][3] += pv.x * vv.w;
            acc[1][0] += pv.y * vv.x; acc[1][1] += pv.y * vv.y;
            acc[1][2] += pv.y * vv.z; acc[1][3] += pv.y * vv.w;
            acc[2][0] += pv.z * vv.x; acc[2][1] += pv.z * vv.y;
            acc[2][2] += pv.z * vv.z; acc[2][3] += pv.z * vv.w;
            acc[3][0] += pv.w * vv.x; acc[3][1] += pv.w * vv.y;
            acc[3][2] += pv.w * vv.z; acc[3][3] += pv.w * vv.w;
        }
        __syncthreads();
    }

    const float gm = gamma[0];
    #pragma unroll
    for (int i = 0; i < 4; i++) {
        #pragma unroll
        for (int j = 0; j < 4; j++) {
            int m = m_base + tm + i;
            int c = tc + j;
            int idx = ((b * 64 + c) << 12) + m;
            out[idx] = gm * acc[i][j] + x[idx];
        }
    }
}

// ---------------------------------------------------------------------------
extern "C" void kernel_launch(void* const* d_in, const int* in_sizes, int n_in,
                              void* d_out, int out_size)
{
    const float* x     = (const float*)d_in[0];
    const float* Wf    = (const float*)d_in[1];
    const float* bf    = (const float*)d_in[2];
    const float* Wg    = (const float*)d_in[3];
    const float* bg    = (const float*)d_in[4];
    const float* Wh    = (const float*)d_in[5];
    const float* bh    = (const float*)d_in[6];
    const float* gamma = (const float*)d_in[7];
    float* out = (float*)d_out;

    kA<<<dim3(32, 4), 256>>>(x, Wf, bf, Wg, bg, Wh, bh);
    kB1<<<dim3(16, 4, 4), 256>>>();
    kB2<<<64, 256>>>();
    kC<<<256, 256>>>(x, gamma, out);
}